// round 7
// baseline (speedup 1.0000x reference)
#include <cuda_runtime.h>
#include <cuda_bf16.h>
#include <math.h>

// Problem constants
#define BB   256                 // batch
#define TT   2048                // seq len
#define VV   128                 // vocab / input size
#define HH   64                  // hidden
#define GG   256                 // 4 gates * HH
#define MM   (BB * TT)           // 524288 rows

// Scratch (device-global; no runtime allocation allowed)
__device__ float g_Wx[VV * GG];            // fused x-part weights [128,256]
__device__ float g_Wh[HH * GG];            // fused h-part weights [64,256]
__device__ float g_bias[GG];               // fused gate biases
__device__ float g_preact[(size_t)MM * GG];  // 512 MB: x-part preactivations
__device__ float g_H[(size_t)MM * HH];       // 128 MB: hidden states per step

__device__ __forceinline__ unsigned int to_tf32(float v) {
    unsigned int r;
    asm("cvt.rna.tf32.f32 %0, %1;" : "=r"(r) : "f"(v));
    return r;
}
__device__ __forceinline__ float tanh_fast(float x) {
    float y;
    asm("tanh.approx.f32 %0, %1;" : "=f"(y) : "f"(x));
    return y;
}
__device__ __forceinline__ unsigned long long pack2(float lo, float hi) {
    unsigned long long r;
    asm("mov.b64 %0, {%1, %2};" : "=l"(r) : "f"(lo), "f"(hi));
    return r;
}
__device__ __forceinline__ void fma2(unsigned long long& acc,
                                     unsigned long long a, unsigned long long b) {
    asm("fma.rn.f32x2 %0, %1, %2, %0;" : "+l"(acc) : "l"(a), "l"(b));
}
__device__ __forceinline__ float sum2(unsigned long long v) {
    float lo, hi;
    asm("mov.b64 {%0, %1}, %2;" : "=f"(lo), "=f"(hi) : "l"(v));
    return lo + hi;
}

// ---------------------------------------------------------------------------
// Kernel 0: pack 4 gate weight matrices into fused layouts.
// Gate order: 0..63 = f, 64..127 = if, 128..191 = ic(tanh), 192..255 = o
// ---------------------------------------------------------------------------
__global__ void pack_weights(const float* __restrict__ Wf,  const float* __restrict__ bf,
                             const float* __restrict__ Wif, const float* __restrict__ bif,
                             const float* __restrict__ Wic, const float* __restrict__ bic,
                             const float* __restrict__ Wo,  const float* __restrict__ bo) {
    int g = blockIdx.x * blockDim.x + threadIdx.x;
    if (g >= GG) return;
    int gate = g >> 6;
    int col  = g & 63;
    const float* W = (gate == 0) ? Wf : (gate == 1) ? Wif : (gate == 2) ? Wic : Wo;
    const float* bv = (gate == 0) ? bf : (gate == 1) ? bif : (gate == 2) ? bic : bo;
    g_bias[g] = bv[col];
    for (int k = 0; k < VV; k++)
        g_Wx[k * GG + g] = W[k * HH + col];
    for (int j = 0; j < HH; j++)
        g_Wh[j * GG + g] = W[(VV + j) * HH + col];
}

// ---------------------------------------------------------------------------
// Kernel 1: preact[m, g] = x[m, :] @ Wx[:, g] + bias[g]   via TF32 mma.sync
// M=524288, N=256, K=128.  BM=128, whole K resident; CTA loops over all 4
// n-blocks of 64 reusing the A tile (x read from DRAM exactly once).
// 8 warps in 4(M) x 2(N); each warp computes 32x32 with m16n8k8 tiles.
// ---------------------------------------------------------------------------
#define AS_STRIDE 132
#define BS_STRIDE 72

__global__ __launch_bounds__(256) void gemm_x(const float* __restrict__ x) {
    extern __shared__ unsigned int smem[];
    unsigned int* As = smem;                       // 128 * 132 words
    unsigned int* Bs = smem + 128 * AS_STRIDE;     // 128 * 72 words

    const int m0 = blockIdx.x * 128;
    const int tid  = threadIdx.x;
    const int lane = tid & 31;
    const int warp = tid >> 5;
    const int wm = warp >> 1;      // 0..3  (M)
    const int wn = warp & 1;       // 0..1  (N)
    const int gp = lane >> 2;      // 0..7
    const int tq = lane & 3;       // 0..3

    // ---- Load A tile: 128 rows x 128 K (fp32 -> tf32). 16 float4 / thread.
    #pragma unroll
    for (int i = 0; i < 16; i++) {
        int t  = tid + i * 256;            // float4 index 0..4095
        int r  = t >> 5;
        int c4 = (t & 31) * 4;
        float4 v = *reinterpret_cast<const float4*>(&x[(size_t)(m0 + r) * VV + c4]);
        unsigned int* dst = &As[r * AS_STRIDE + c4];
        dst[0] = to_tf32(v.x); dst[1] = to_tf32(v.y);
        dst[2] = to_tf32(v.z); dst[3] = to_tf32(v.w);
    }

    for (int nb = 0; nb < 4; nb++) {
        const int n0 = nb * 64;
        __syncthreads();   // A ready (first iter) / prev mma done with Bs

        // ---- Load B tile: 128 K x 64 N (fp32 -> tf32). 8 float4 / thread.
        #pragma unroll
        for (int i = 0; i < 8; i++) {
            int t  = tid + i * 256;            // float4 index 0..2047
            int k  = t >> 4;
            int c4 = (t & 15) * 4;
            float4 v = *reinterpret_cast<const float4*>(&g_Wx[(size_t)k * GG + n0 + c4]);
            unsigned int* dst = &Bs[k * BS_STRIDE + c4];
            dst[0] = to_tf32(v.x); dst[1] = to_tf32(v.y);
            dst[2] = to_tf32(v.z); dst[3] = to_tf32(v.w);
        }
        __syncthreads();

        float acc[2][4][4] = {};

        #pragma unroll 4
        for (int ks = 0; ks < 16; ks++) {
            const int k0 = ks * 8;
            unsigned int bfr[4][2];
            #pragma unroll
            for (int ni = 0; ni < 4; ni++) {
                int col = wn * 32 + ni * 8 + gp;
                bfr[ni][0] = Bs[(k0 + tq)     * BS_STRIDE + col];
                bfr[ni][1] = Bs[(k0 + tq + 4) * BS_STRIDE + col];
            }
            #pragma unroll
            for (int mi = 0; mi < 2; mi++) {
                int row = wm * 32 + mi * 16 + gp;
                unsigned int a0 = As[row       * AS_STRIDE + k0 + tq];
                unsigned int a1 = As[(row + 8) * AS_STRIDE + k0 + tq];
                unsigned int a2 = As[row       * AS_STRIDE + k0 + tq + 4];
                unsigned int a3 = As[(row + 8) * AS_STRIDE + k0 + tq + 4];
                #pragma unroll
                for (int ni = 0; ni < 4; ni++) {
                    asm volatile(
                        "mma.sync.aligned.m16n8k8.row.col.f32.tf32.tf32.f32 "
                        "{%0,%1,%2,%3}, {%4,%5,%6,%7}, {%8,%9}, {%0,%1,%2,%3};"
                        : "+f"(acc[mi][ni][0]), "+f"(acc[mi][ni][1]),
                          "+f"(acc[mi][ni][2]), "+f"(acc[mi][ni][3])
                        : "r"(a0), "r"(a1), "r"(a2), "r"(a3),
                          "r"(bfr[ni][0]), "r"(bfr[ni][1]));
                }
            }
        }

        // ---- Epilogue: bias + store (float2 per fragment-row)
        #pragma unroll
        for (int ni = 0; ni < 4; ni++) {
            int bcol = n0 + wn * 32 + ni * 8 + 2 * tq;
            float bv0 = g_bias[bcol];
            float bv1 = g_bias[bcol + 1];
            #pragma unroll
            for (int mi = 0; mi < 2; mi++) {
                int row = m0 + wm * 32 + mi * 16 + gp;
                float2 o0 = make_float2(acc[mi][ni][0] + bv0, acc[mi][ni][1] + bv1);
                float2 o1 = make_float2(acc[mi][ni][2] + bv0, acc[mi][ni][3] + bv1);
                *reinterpret_cast<float2*>(&g_preact[(size_t)row * GG + bcol]) = o0;
                *reinterpret_cast<float2*>(&g_preact[(size_t)(row + 8) * GG + bcol]) = o1;
            }
        }
    }
}

// ---------------------------------------------------------------------------
// Kernel 2: recurrent LSTM. One CTA per TWO batch rows (128 CTAs = 1 wave,
// 1 CTA/SM, balanced). 256 threads, thread = gate column for both rows.
// h@Wh via packed fma.rn.f32x2 (FFMA2): 2x fewer FMA issue slots.
// Barriers amortized across the two interleaved recurrences.
// ---------------------------------------------------------------------------
__global__ __launch_bounds__(256, 1) void lstm_kernel() {
    const int b0 = blockIdx.x * 2;
    const int g  = threadIdx.x;

    __shared__ __align__(16) float h_s[2][HH];
    __shared__ float gates_s[2][GG];

    // Load this thread's W_h column, packed as 32 f32x2 pairs
    unsigned long long wh2[HH / 2];
    #pragma unroll
    for (int j = 0; j < HH; j += 2)
        wh2[j >> 1] = pack2(g_Wh[j * GG + g], g_Wh[(j + 1) * GG + g]);

    float c0 = 0.f, c1 = 0.f;
    if (g < HH) { h_s[0][g] = 0.f; h_s[1][g] = 0.f; }
    __syncthreads();

    const float* paA = g_preact + (size_t)b0 * TT * GG + g;
    const float* paB = g_preact + (size_t)(b0 + 1) * TT * GG + g;
    float* houtA = g_H + (size_t)b0 * TT * HH;
    float* houtB = g_H + (size_t)(b0 + 1) * TT * HH;

    // sigmoid(v) = 0.5*tanh(0.5v)+0.5 ; tanh gate uses (1,1,0)
    const bool is_tanh_gate = ((g >> 6) == 2);
    const float pre    = is_tanh_gate ? 1.f : 0.5f;
    const float post_m = is_tanh_gate ? 1.f : 0.5f;
    const float post_b = is_tanh_gate ? 0.f : 0.5f;

    // 2-deep prefetch per row (lstm is issue-bound; modest depth suffices)
    float fA0 = __ldg(paA), fA1 = __ldg(paA + GG);
    float fB0 = __ldg(paB), fB1 = __ldg(paB + GG);

    const ulonglong2* h2A = reinterpret_cast<const ulonglong2*>(h_s[0]);
    const ulonglong2* h2B = reinterpret_cast<const ulonglong2*>(h_s[1]);

    for (int t = 0; t < TT; t++) {
        float pA = fA0, pB = fB0;
        fA0 = fA1; fB0 = fB1;
        int tn = (t + 2 < TT) ? (t + 2) : (TT - 1);
        fA1 = __ldg(paA + (size_t)tn * GG);
        fB1 = __ldg(paB + (size_t)tn * GG);

        // v = preact + h @ Wh[:, g]  for both rows, packed f32x2
        unsigned long long aA0 = pack2(pA, 0.f), aA1 = pack2(0.f, 0.f);
        unsigned long long aB0 = pack2(pB, 0.f), aB1 = pack2(0.f, 0.f);
        #pragma unroll
        for (int jj = 0; jj < HH / 4; jj++) {
            ulonglong2 hvA = h2A[jj];
            ulonglong2 hvB = h2B[jj];
            fma2(aA0, hvA.x, wh2[2 * jj]);
            fma2(aA1, hvA.y, wh2[2 * jj + 1]);
            fma2(aB0, hvB.x, wh2[2 * jj]);
            fma2(aB1, hvB.y, wh2[2 * jj + 1]);
        }
        float vA = sum2(aA0) + sum2(aA1);
        float vB = sum2(aB0) + sum2(aB1);

        gates_s[0][g] = fmaf(tanh_fast(vA * pre), post_m, post_b);
        gates_s[1][g] = fmaf(tanh_fast(vB * pre), post_m, post_b);
        __syncthreads();

        if (g < HH) {
            float f0v  = gates_s[0][g];
            float af0  = gates_s[0][HH + g];
            float add0 = gates_s[0][2 * HH + g];
            float o0   = gates_s[0][3 * HH + g];
            c0 = fmaf(c0, f0v, add0 * af0);
            float hn0 = tanh_fast(c0) * o0;
            h_s[0][g] = hn0;
            houtA[(size_t)t * HH + g] = hn0;

            float f1v  = gates_s[1][g];
            float af1  = gates_s[1][HH + g];
            float add1 = gates_s[1][2 * HH + g];
            float o1   = gates_s[1][3 * HH + g];
            c1 = fmaf(c1, f1v, add1 * af1);
            float hn1 = tanh_fast(c1) * o1;
            h_s[1][g] = hn1;
            houtB[(size_t)t * HH + g] = hn1;
        }
        __syncthreads();
    }
}

// ---------------------------------------------------------------------------
// Kernel 3: out[m, :] = softmax(h[m, :] @ W_out + b_out)  via TF32 mma
// CTA = 128 rows, 256 threads / 8 warps; warp = 16 rows x full N=128, K=64.
// Softmax on fragments: row's 128 logits live in 4 lanes (quad shfl reduce).
// ---------------------------------------------------------------------------
#define HS_STRIDE 68
#define WS_STRIDE 136

__global__ __launch_bounds__(256, 2) void out_proj(const float* __restrict__ Wout,
                                                   const float* __restrict__ bout,
                                                   float* __restrict__ out) {
    extern __shared__ unsigned int sm[];
    unsigned int* Hs = sm;                                 // 128 * 68 words
    unsigned int* Ws = sm + 128 * HS_STRIDE;               // 64 * 136 words
    float* bs = (float*)(sm + 128 * HS_STRIDE + 64 * WS_STRIDE);  // 128 floats

    const int r0   = blockIdx.x * 128;
    const int tid  = threadIdx.x;
    const int lane = tid & 31;
    const int warp = tid >> 5;
    const int gp = lane >> 2;      // 0..7
    const int tq = lane & 3;       // 0..3

    // Load h tile: 128 rows x 64 (fp32 -> tf32). 8 float4 / thread.
    #pragma unroll
    for (int i = 0; i < 8; i++) {
        int t  = tid + i * 256;        // 0..2047
        int r  = t >> 4;
        int c4 = (t & 15) * 4;
        float4 v = *reinterpret_cast<const float4*>(&g_H[(size_t)(r0 + r) * HH + c4]);
        unsigned int* d = &Hs[r * HS_STRIDE + c4];
        d[0] = to_tf32(v.x); d[1] = to_tf32(v.y);
        d[2] = to_tf32(v.z); d[3] = to_tf32(v.w);
    }
    // Load W_out [64 K x 128 N]. 8 float4 / thread.
    #pragma unroll
    for (int i = 0; i < 8; i++) {
        int t  = tid + i * 256;
        int k  = t >> 5;
        int c4 = (t & 31) * 4;
        float4 v = *reinterpret_cast<const float4*>(&Wout[k * VV + c4]);
        unsigned int* d = &Ws[k * WS_STRIDE + c4];
        d[0] = to_tf32(v.x); d[1] = to_tf32(v.y);
        d[2] = to_tf32(v.z); d[3] = to_tf32(v.w);
    }
    if (tid < VV) bs[tid] = bout[tid];
    __syncthreads();

    float acc[16][4] = {};
    const int rowA = warp * 16 + gp;

    #pragma unroll
    for (int ks = 0; ks < 8; ks++) {
        const int k0 = ks * 8;
        unsigned int a0 = Hs[rowA       * HS_STRIDE + k0 + tq];
        unsigned int a1 = Hs[(rowA + 8) * HS_STRIDE + k0 + tq];
        unsigned int a2 = Hs[rowA       * HS_STRIDE + k0 + tq + 4];
        unsigned int a3 = Hs[(rowA + 8) * HS_STRIDE + k0 + tq + 4];
        #pragma unroll
        for (int ni = 0; ni < 16; ni++) {
            unsigned int b0 = Ws[(k0 + tq)     * WS_STRIDE + ni * 8 + gp];
            unsigned int b1 = Ws[(k0 + tq + 4) * WS_STRIDE + ni * 8 + gp];
            asm volatile(
                "mma.sync.aligned.m16n8k8.row.col.f32.tf32.tf32.f32 "
                "{%0,%1,%2,%3}, {%4,%5,%6,%7}, {%8,%9}, {%0,%1,%2,%3};"
                : "+f"(acc[ni][0]), "+f"(acc[ni][1]),
                  "+f"(acc[ni][2]), "+f"(acc[ni][3])
                : "r"(a0), "r"(a1), "r"(a2), "r"(a3), "r"(b0), "r"(b1));
        }
    }

    // Softmax: thread holds rows (rowA, rowA+8); row's logits in 4 lanes (tq).
    #pragma unroll
    for (int rr = 0; rr < 2; rr++) {
        float l[32];
        #pragma unroll
        for (int ni = 0; ni < 16; ni++) {
            float b0 = bs[ni * 8 + 2 * tq];
            float b1 = bs[ni * 8 + 2 * tq + 1];
            l[2 * ni]     = acc[ni][2 * rr]     + b0;
            l[2 * ni + 1] = acc[ni][2 * rr + 1] + b1;
        }
        float mx = l[0];
        #pragma unroll
        for (int i = 1; i < 32; i++) mx = fmaxf(mx, l[i]);
        mx = fmaxf(mx, __shfl_xor_sync(0xFFFFFFFFu, mx, 1));
        mx = fmaxf(mx, __shfl_xor_sync(0xFFFFFFFFu, mx, 2));

        float s = 0.f;
        #pragma unroll
        for (int i = 0; i < 32; i++) { l[i] = __expf(l[i] - mx); s += l[i]; }
        s += __shfl_xor_sync(0xFFFFFFFFu, s, 1);
        s += __shfl_xor_sync(0xFFFFFFFFu, s, 2);
        float inv = __fdividef(1.f, s);

        size_t row = (size_t)(r0 + rowA + rr * 8);
        #pragma unroll
        for (int ni = 0; ni < 16; ni++) {
            float2 o = make_float2(l[2 * ni] * inv, l[2 * ni + 1] * inv);
            *reinterpret_cast<float2*>(&out[row * VV + ni * 8 + 2 * tq]) = o;
        }
    }
}

// ---------------------------------------------------------------------------
// Launch
// ---------------------------------------------------------------------------
extern "C" void kernel_launch(void* const* d_in, const int* in_sizes, int n_in,
                              void* d_out, int out_size) {
    const float* x    = (const float*)d_in[0];
    const float* Wf   = (const float*)d_in[1];
    const float* bf   = (const float*)d_in[2];
    const float* Wif  = (const float*)d_in[3];
    const float* bif  = (const float*)d_in[4];
    const float* Wic  = (const float*)d_in[5];
    const float* bic  = (const float*)d_in[6];
    const float* Wo   = (const float*)d_in[7];
    const float* bo   = (const float*)d_in[8];
    const float* Wout = (const float*)d_in[9];
    const float* bout = (const float*)d_in[10];
    float* out = (float*)d_out;

    const int gemm_smem = (128 * AS_STRIDE + 128 * BS_STRIDE) * 4;         // 104448 B
    const int proj_smem = (128 * HS_STRIDE + 64 * WS_STRIDE + 128) * 4;    // 70144 B
    cudaFuncSetAttribute(gemm_x, cudaFuncAttributeMaxDynamicSharedMemorySize,
                         gemm_smem);
    cudaFuncSetAttribute(out_proj, cudaFuncAttributeMaxDynamicSharedMemorySize,
                         proj_smem);

    pack_weights<<<1, 256>>>(Wf, bf, Wif, bif, Wic, bic, Wo, bo);
    gemm_x<<<MM / 128, 256, gemm_smem>>>(x);
    lstm_kernel<<<BB / 2, 256>>>();
    out_proj<<<MM / 128, 256, proj_smem>>>(Wout, bout, out);
}

// round 8
// speedup vs baseline: 1.2256x; 1.2256x over previous
#include <cuda_runtime.h>
#include <cuda_bf16.h>
#include <math.h>

// Problem constants
#define BB   256                 // batch
#define TT   2048                // seq len
#define VV   128                 // vocab / input size
#define HH   64                  // hidden
#define GG   256                 // 4 gates * HH
#define MM   (BB * TT)           // 524288 rows

// Scratch (device-global; no runtime allocation allowed)
__device__ float g_Wx[VV * GG];            // fused x-part weights [128,256]
__device__ float g_Wh[HH * GG];            // fused h-part weights [64,256]
__device__ float g_bias[GG];               // fused gate biases
__device__ float g_preact[(size_t)MM * GG];  // 512 MB: x-part preactivations
__device__ float g_H[(size_t)MM * HH];       // 128 MB: hidden states per step

__device__ __forceinline__ unsigned int to_tf32(float v) {
    unsigned int r;
    asm("cvt.rna.tf32.f32 %0, %1;" : "=r"(r) : "f"(v));
    return r;
}
__device__ __forceinline__ float tanh_fast(float x) {
    float y;
    asm("tanh.approx.f32 %0, %1;" : "=f"(y) : "f"(x));
    return y;
}
__device__ __forceinline__ unsigned long long pack2(float lo, float hi) {
    unsigned long long r;
    asm("mov.b64 %0, {%1, %2};" : "=l"(r) : "f"(lo), "f"(hi));
    return r;
}
__device__ __forceinline__ void fma2(unsigned long long& acc,
                                     unsigned long long a, unsigned long long b) {
    asm("fma.rn.f32x2 %0, %1, %2, %0;" : "+l"(acc) : "l"(a), "l"(b));
}
__device__ __forceinline__ float sum2(unsigned long long v) {
    float lo, hi;
    asm("mov.b64 {%0, %1}, %2;" : "=f"(lo), "=f"(hi) : "l"(v));
    return lo + hi;
}

// ---------------------------------------------------------------------------
// Kernel 0: pack 4 gate weight matrices into fused layouts.
// Gate order: 0..63 = f, 64..127 = if, 128..191 = ic(tanh), 192..255 = o
// ---------------------------------------------------------------------------
__global__ void pack_weights(const float* __restrict__ Wf,  const float* __restrict__ bf,
                             const float* __restrict__ Wif, const float* __restrict__ bif,
                             const float* __restrict__ Wic, const float* __restrict__ bic,
                             const float* __restrict__ Wo,  const float* __restrict__ bo) {
    int g = blockIdx.x * blockDim.x + threadIdx.x;
    if (g >= GG) return;
    int gate = g >> 6;
    int col  = g & 63;
    const float* W = (gate == 0) ? Wf : (gate == 1) ? Wif : (gate == 2) ? Wic : Wo;
    const float* bv = (gate == 0) ? bf : (gate == 1) ? bif : (gate == 2) ? bic : bo;
    g_bias[g] = bv[col];
    for (int k = 0; k < VV; k++)
        g_Wx[k * GG + g] = W[k * HH + col];
    for (int j = 0; j < HH; j++)
        g_Wh[j * GG + g] = W[(VV + j) * HH + col];
}

// ---------------------------------------------------------------------------
// Kernel 1: preact[m, g] = x[m, :] @ Wx[:, g] + bias[g]   via TF32 mma.sync
// M=524288, N=256, K=128.  BM=128, whole K resident; CTA loops over all 4
// n-blocks of 64 reusing the A tile (x read from DRAM exactly once).
// 8 warps in 4(M) x 2(N); each warp computes 32x32 with m16n8k8 tiles.
// ---------------------------------------------------------------------------
#define AS_STRIDE 132
#define BS_STRIDE 72

__global__ __launch_bounds__(256) void gemm_x(const float* __restrict__ x) {
    extern __shared__ unsigned int smem[];
    unsigned int* As = smem;                       // 128 * 132 words
    unsigned int* Bs = smem + 128 * AS_STRIDE;     // 128 * 72 words

    const int m0 = blockIdx.x * 128;
    const int tid  = threadIdx.x;
    const int lane = tid & 31;
    const int warp = tid >> 5;
    const int wm = warp >> 1;      // 0..3  (M)
    const int wn = warp & 1;       // 0..1  (N)
    const int gp = lane >> 2;      // 0..7
    const int tq = lane & 3;       // 0..3

    // ---- Load A tile: 128 rows x 128 K (fp32 -> tf32). 16 float4 / thread.
    #pragma unroll
    for (int i = 0; i < 16; i++) {
        int t  = tid + i * 256;            // float4 index 0..4095
        int r  = t >> 5;
        int c4 = (t & 31) * 4;
        float4 v = *reinterpret_cast<const float4*>(&x[(size_t)(m0 + r) * VV + c4]);
        unsigned int* dst = &As[r * AS_STRIDE + c4];
        dst[0] = to_tf32(v.x); dst[1] = to_tf32(v.y);
        dst[2] = to_tf32(v.z); dst[3] = to_tf32(v.w);
    }

    for (int nb = 0; nb < 4; nb++) {
        const int n0 = nb * 64;
        __syncthreads();   // A ready (first iter) / prev mma done with Bs

        // ---- Load B tile: 128 K x 64 N (fp32 -> tf32). 8 float4 / thread.
        #pragma unroll
        for (int i = 0; i < 8; i++) {
            int t  = tid + i * 256;            // float4 index 0..2047
            int k  = t >> 4;
            int c4 = (t & 15) * 4;
            float4 v = *reinterpret_cast<const float4*>(&g_Wx[(size_t)k * GG + n0 + c4]);
            unsigned int* dst = &Bs[k * BS_STRIDE + c4];
            dst[0] = to_tf32(v.x); dst[1] = to_tf32(v.y);
            dst[2] = to_tf32(v.z); dst[3] = to_tf32(v.w);
        }
        __syncthreads();

        float acc[2][4][4] = {};

        #pragma unroll 4
        for (int ks = 0; ks < 16; ks++) {
            const int k0 = ks * 8;
            unsigned int bfr[4][2];
            #pragma unroll
            for (int ni = 0; ni < 4; ni++) {
                int col = wn * 32 + ni * 8 + gp;
                bfr[ni][0] = Bs[(k0 + tq)     * BS_STRIDE + col];
                bfr[ni][1] = Bs[(k0 + tq + 4) * BS_STRIDE + col];
            }
            #pragma unroll
            for (int mi = 0; mi < 2; mi++) {
                int row = wm * 32 + mi * 16 + gp;
                unsigned int a0 = As[row       * AS_STRIDE + k0 + tq];
                unsigned int a1 = As[(row + 8) * AS_STRIDE + k0 + tq];
                unsigned int a2 = As[row       * AS_STRIDE + k0 + tq + 4];
                unsigned int a3 = As[(row + 8) * AS_STRIDE + k0 + tq + 4];
                #pragma unroll
                for (int ni = 0; ni < 4; ni++) {
                    asm volatile(
                        "mma.sync.aligned.m16n8k8.row.col.f32.tf32.tf32.f32 "
                        "{%0,%1,%2,%3}, {%4,%5,%6,%7}, {%8,%9}, {%0,%1,%2,%3};"
                        : "+f"(acc[mi][ni][0]), "+f"(acc[mi][ni][1]),
                          "+f"(acc[mi][ni][2]), "+f"(acc[mi][ni][3])
                        : "r"(a0), "r"(a1), "r"(a2), "r"(a3),
                          "r"(bfr[ni][0]), "r"(bfr[ni][1]));
                }
            }
        }

        // ---- Epilogue: bias + store (float2 per fragment-row)
        #pragma unroll
        for (int ni = 0; ni < 4; ni++) {
            int bcol = n0 + wn * 32 + ni * 8 + 2 * tq;
            float bv0 = g_bias[bcol];
            float bv1 = g_bias[bcol + 1];
            #pragma unroll
            for (int mi = 0; mi < 2; mi++) {
                int row = m0 + wm * 32 + mi * 16 + gp;
                float2 o0 = make_float2(acc[mi][ni][0] + bv0, acc[mi][ni][1] + bv1);
                float2 o1 = make_float2(acc[mi][ni][2] + bv0, acc[mi][ni][3] + bv1);
                *reinterpret_cast<float2*>(&g_preact[(size_t)row * GG + bcol]) = o0;
                *reinterpret_cast<float2*>(&g_preact[(size_t)(row + 8) * GG + bcol]) = o1;
            }
        }
    }
}

// ---------------------------------------------------------------------------
// Kernel 2: recurrent LSTM. One CTA per batch row (256 CTAs, occ 2).
// Thread tid owns gate (tid&3) of column (tid>>2): the 4 gates of a column
// live in one lane-quad -> gate exchange via SHFL.IDX (no gates SMEM, no
// barrier #1). All threads do the c/h update redundantly (register c per
// quad). h double-buffered in SMEM -> ONE __syncthreads per step.
// h@Wh via packed fma.rn.f32x2.
// ---------------------------------------------------------------------------
__global__ __launch_bounds__(256, 2) void lstm_kernel() {
    const int b    = blockIdx.x;
    const int tid  = threadIdx.x;
    const int col  = tid >> 2;          // 0..63
    const int gate = tid & 3;           // 0:f 1:if 2:ic(tanh) 3:o
    const int g    = gate * 64 + col;   // fused gate index
    const int lane = tid & 31;
    const int qbase = lane & ~3;        // quad base lane

    __shared__ __align__(16) float h_s[2][HH];

    // This thread's W_h column, packed as 32 f32x2 pairs
    unsigned long long wh2[HH / 2];
    #pragma unroll
    for (int j = 0; j < HH; j += 2)
        wh2[j >> 1] = pack2(g_Wh[j * GG + g], g_Wh[(j + 1) * GG + g]);

    float c = 0.f;
    if (tid < HH) { h_s[0][tid] = 0.f; h_s[1][tid] = 0.f; }
    __syncthreads();

    const float* pa = g_preact + (size_t)b * TT * GG + g;
    float* hout = g_H + (size_t)b * TT * HH + col;

    // sigmoid(v) = 0.5*tanh(0.5v)+0.5 ; tanh gate (gate==2) uses (1,1,0)
    const float pre    = (gate == 2) ? 1.f : 0.5f;
    const float post_m = (gate == 2) ? 1.f : 0.5f;
    const float post_b = (gate == 2) ? 0.f : 0.5f;

    // 2-deep preact prefetch
    float f0 = __ldg(pa);
    float f1 = __ldg(pa + GG);

    for (int t = 0; t < TT; t++) {
        float p = f0;
        f0 = f1;
        int tn = (t + 2 < TT) ? (t + 2) : (TT - 1);
        f1 = __ldg(pa + (size_t)tn * GG);

        // v = preact + h @ Wh[:, g]   (packed f32x2, 2 accumulators)
        const ulonglong2* h2 = reinterpret_cast<const ulonglong2*>(h_s[t & 1]);
        unsigned long long a0 = pack2(p, 0.f), a1 = pack2(0.f, 0.f);
        #pragma unroll
        for (int jj = 0; jj < HH / 4; jj++) {
            ulonglong2 hv = h2[jj];
            fma2(a0, hv.x, wh2[2 * jj]);
            fma2(a1, hv.y, wh2[2 * jj + 1]);
        }
        float v = sum2(a0) + sum2(a1);

        float val = fmaf(tanh_fast(v * pre), post_m, post_b);

        // Quad gather: gate k of this column lives in lane qbase+k
        float fv  = __shfl_sync(0xFFFFFFFFu, val, qbase + 0);
        float af  = __shfl_sync(0xFFFFFFFFu, val, qbase + 1);
        float add = __shfl_sync(0xFFFFFFFFu, val, qbase + 2);
        float ov  = __shfl_sync(0xFFFFFFFFu, val, qbase + 3);

        // Redundant per-quad update (c identical across the 4 lanes)
        c = fmaf(c, fv, add * af);
        float hn = tanh_fast(c) * ov;

        if (gate == 0) {
            h_s[(t + 1) & 1][col] = hn;
            hout[(size_t)t * HH] = hn;
        }
        __syncthreads();
    }
}

// ---------------------------------------------------------------------------
// Kernel 3: out[m, :] = softmax(h[m, :] @ W_out + b_out)  via TF32 mma
// CTA = 128 rows, 256 threads / 8 warps; warp = 16 rows x full N=128, K=64.
// Softmax on fragments: row's 128 logits live in 4 lanes (quad shfl reduce).
// ---------------------------------------------------------------------------
#define HS_STRIDE 68
#define WS_STRIDE 136

__global__ __launch_bounds__(256, 2) void out_proj(const float* __restrict__ Wout,
                                                   const float* __restrict__ bout,
                                                   float* __restrict__ out) {
    extern __shared__ unsigned int sm[];
    unsigned int* Hs = sm;                                 // 128 * 68 words
    unsigned int* Ws = sm + 128 * HS_STRIDE;               // 64 * 136 words
    float* bs = (float*)(sm + 128 * HS_STRIDE + 64 * WS_STRIDE);  // 128 floats

    const int r0   = blockIdx.x * 128;
    const int tid  = threadIdx.x;
    const int lane = tid & 31;
    const int warp = tid >> 5;
    const int gp = lane >> 2;      // 0..7
    const int tq = lane & 3;       // 0..3

    // Load h tile: 128 rows x 64 (fp32 -> tf32). 8 float4 / thread.
    #pragma unroll
    for (int i = 0; i < 8; i++) {
        int t  = tid + i * 256;        // 0..2047
        int r  = t >> 4;
        int c4 = (t & 15) * 4;
        float4 v = *reinterpret_cast<const float4*>(&g_H[(size_t)(r0 + r) * HH + c4]);
        unsigned int* d = &Hs[r * HS_STRIDE + c4];
        d[0] = to_tf32(v.x); d[1] = to_tf32(v.y);
        d[2] = to_tf32(v.z); d[3] = to_tf32(v.w);
    }
    // Load W_out [64 K x 128 N]. 8 float4 / thread.
    #pragma unroll
    for (int i = 0; i < 8; i++) {
        int t  = tid + i * 256;
        int k  = t >> 5;
        int c4 = (t & 31) * 4;
        float4 v = *reinterpret_cast<const float4*>(&Wout[k * VV + c4]);
        unsigned int* d = &Ws[k * WS_STRIDE + c4];
        d[0] = to_tf32(v.x); d[1] = to_tf32(v.y);
        d[2] = to_tf32(v.z); d[3] = to_tf32(v.w);
    }
    if (tid < VV) bs[tid] = bout[tid];
    __syncthreads();

    float acc[16][4] = {};
    const int rowA = warp * 16 + gp;

    #pragma unroll
    for (int ks = 0; ks < 8; ks++) {
        const int k0 = ks * 8;
        unsigned int a0 = Hs[rowA       * HS_STRIDE + k0 + tq];
        unsigned int a1 = Hs[(rowA + 8) * HS_STRIDE + k0 + tq];
        unsigned int a2 = Hs[rowA       * HS_STRIDE + k0 + tq + 4];
        unsigned int a3 = Hs[(rowA + 8) * HS_STRIDE + k0 + tq + 4];
        #pragma unroll
        for (int ni = 0; ni < 16; ni++) {
            unsigned int b0 = Ws[(k0 + tq)     * WS_STRIDE + ni * 8 + gp];
            unsigned int b1 = Ws[(k0 + tq + 4) * WS_STRIDE + ni * 8 + gp];
            asm volatile(
                "mma.sync.aligned.m16n8k8.row.col.f32.tf32.tf32.f32 "
                "{%0,%1,%2,%3}, {%4,%5,%6,%7}, {%8,%9}, {%0,%1,%2,%3};"
                : "+f"(acc[ni][0]), "+f"(acc[ni][1]),
                  "+f"(acc[ni][2]), "+f"(acc[ni][3])
                : "r"(a0), "r"(a1), "r"(a2), "r"(a3), "r"(b0), "r"(b1));
        }
    }

    // Softmax: thread holds rows (rowA, rowA+8); row's logits in 4 lanes (tq).
    #pragma unroll
    for (int rr = 0; rr < 2; rr++) {
        float l[32];
        #pragma unroll
        for (int ni = 0; ni < 16; ni++) {
            float b0 = bs[ni * 8 + 2 * tq];
            float b1 = bs[ni * 8 + 2 * tq + 1];
            l[2 * ni]     = acc[ni][2 * rr]     + b0;
            l[2 * ni + 1] = acc[ni][2 * rr + 1] + b1;
        }
        float mx = l[0];
        #pragma unroll
        for (int i = 1; i < 32; i++) mx = fmaxf(mx, l[i]);
        mx = fmaxf(mx, __shfl_xor_sync(0xFFFFFFFFu, mx, 1));
        mx = fmaxf(mx, __shfl_xor_sync(0xFFFFFFFFu, mx, 2));

        float s = 0.f;
        #pragma unroll
        for (int i = 0; i < 32; i++) { l[i] = __expf(l[i] - mx); s += l[i]; }
        s += __shfl_xor_sync(0xFFFFFFFFu, s, 1);
        s += __shfl_xor_sync(0xFFFFFFFFu, s, 2);
        float inv = __fdividef(1.f, s);

        size_t row = (size_t)(r0 + rowA + rr * 8);
        #pragma unroll
        for (int ni = 0; ni < 16; ni++) {
            float2 o = make_float2(l[2 * ni] * inv, l[2 * ni + 1] * inv);
            *reinterpret_cast<float2*>(&out[row * VV + ni * 8 + 2 * tq]) = o;
        }
    }
}

// ---------------------------------------------------------------------------
// Launch
// ---------------------------------------------------------------------------
extern "C" void kernel_launch(void* const* d_in, const int* in_sizes, int n_in,
                              void* d_out, int out_size) {
    const float* x    = (const float*)d_in[0];
    const float* Wf   = (const float*)d_in[1];
    const float* bf   = (const float*)d_in[2];
    const float* Wif  = (const float*)d_in[3];
    const float* bif  = (const float*)d_in[4];
    const float* Wic  = (const float*)d_in[5];
    const float* bic  = (const float*)d_in[6];
    const float* Wo   = (const float*)d_in[7];
    const float* bo   = (const float*)d_in[8];
    const float* Wout = (const float*)d_in[9];
    const float* bout = (const float*)d_in[10];
    float* out = (float*)d_out;

    const int gemm_smem = (128 * AS_STRIDE + 128 * BS_STRIDE) * 4;         // 104448 B
    const int proj_smem = (128 * HS_STRIDE + 64 * WS_STRIDE + 128) * 4;    // 70144 B
    cudaFuncSetAttribute(gemm_x, cudaFuncAttributeMaxDynamicSharedMemorySize,
                         gemm_smem);
    cudaFuncSetAttribute(out_proj, cudaFuncAttributeMaxDynamicSharedMemorySize,
                         proj_smem);

    pack_weights<<<1, 256>>>(Wf, bf, Wif, bif, Wic, bic, Wo, bo);
    gemm_x<<<MM / 128, 256, gemm_smem>>>(x);
    lstm_kernel<<<BB, 256>>>();
    out_proj<<<MM / 128, 256, proj_smem>>>(Wout, bout, out);
}